// round 6
// baseline (speedup 1.0000x reference)
#include <cuda_runtime.h>
#include <cstdint>

#define NB 4
#define LL 4096
#define HH 16
#define DD 64
#define MM 64
#define CC 128
#define GG 32
#define NTILE (NB*GG*HH)   // 2048
#define EPS 1e-6f

// smem strides (floats)
#define SA 68   // row-pattern A loads (sq, sk)
#define SB 72   // col-pattern B loads (sv, skvp; k_state tiles)
#define SSW 132 // S tile stride

__device__ float g_kv [NTILE*DD*MM];
__device__ float g_kvp[NTILE*DD*MM];
__device__ float g_ks [NTILE*DD];
__device__ float g_ksp[NTILE*DD];

__device__ __forceinline__ float phi(float x) { return x > 0.f ? x + 1.f : __expf(x); }
__device__ __forceinline__ float f2tf(float f) {
    uint32_t r; asm("cvt.rna.tf32.f32 %0, %1;" : "=r"(r) : "f"(f)); return __uint_as_float(r);
}
__device__ __forceinline__ void mma8(float c[4], uint32_t a0, uint32_t a1, uint32_t a2, uint32_t a3,
                                     uint32_t b0, uint32_t b1) {
    asm volatile("mma.sync.aligned.m16n8k8.row.col.f32.tf32.tf32.f32 "
                 "{%0,%1,%2,%3},{%4,%5,%6,%7},{%8,%9},{%0,%1,%2,%3};"
                 : "+f"(c[0]), "+f"(c[1]), "+f"(c[2]), "+f"(c[3])
                 : "r"(a0), "r"(a1), "r"(a2), "r"(a3), "r"(b0), "r"(b1));
}

// ---------------------------------------------------------------------------
// k_state: kv[d][m] = sum_c phi(k)[c][d] * v[c][m]  (M=64,N=64,K=128)
//          ksum[d] = sum_c phi(k)[c][d]
// 256 threads (8 warps, 16x32 warp tiles), 3 CTAs/SM.
// ---------------------------------------------------------------------------
#define SMEM1 ((2*CC*SB + 256) * 4)

__global__ __launch_bounds__(256, 3)
void k_state(const float* __restrict__ K, const float* __restrict__ V) {
    extern __shared__ float sm[];
    float* sk   = sm;
    float* sv   = sm + CC * SB;
    float* sred = sm + 2 * CC * SB;   // 4 x 64 partial ksums
    const int tid = threadIdx.x, wid = tid >> 5, lane = tid & 31;
    const int gid = lane >> 2, tg = lane & 3;
    const int b = blockIdx.x, h = b & 15, g = (b >> 4) & 31, n = b >> 9;

    #pragma unroll
    for (int it = 0; it < 8; it++) {
        int idx = tid + it * 256;
        int r = idx >> 4, c0 = (idx & 15) * 4;
        int gb = ((n * LL + g * CC + r) * HH + h) * DD + c0;
        float4 k4 = *(const float4*)(K + gb);
        float4 v4 = *(const float4*)(V + gb);
        sk[r * SB + c0 + 0] = f2tf(phi(k4.x));
        sk[r * SB + c0 + 1] = f2tf(phi(k4.y));
        sk[r * SB + c0 + 2] = f2tf(phi(k4.z));
        sk[r * SB + c0 + 3] = f2tf(phi(k4.w));
        sv[r * SB + c0 + 0] = f2tf(v4.x);
        sv[r * SB + c0 + 1] = f2tf(v4.y);
        sv[r * SB + c0 + 2] = f2tf(v4.z);
        sv[r * SB + c0 + 3] = f2tf(v4.w);
    }
    __syncthreads();

    // ksum partials: thread handles 32 rows of one d
    {
        int d = tid & 63, part = tid >> 6;
        float s = 0.f;
        #pragma unroll 8
        for (int c = part * 32; c < part * 32 + 32; c++) s += sk[c * SB + d];
        sred[part * 64 + d] = s;
    }

    // GEMM: warp tile rows d0..d0+15, cols oc..oc+31, K=128
    const int d0 = (wid >> 1) * 16, oc = (wid & 1) * 32;
    float cD[4][4];
    #pragma unroll
    for (int nj = 0; nj < 4; nj++)
        #pragma unroll
        for (int q = 0; q < 4; q++) cD[nj][q] = 0.f;

    #pragma unroll
    for (int kk = 0; kk < 16; kk++) {
        int kr = kk * 8 + tg;
        uint32_t a0 = __float_as_uint(sk[kr * SB + d0 + gid]);
        uint32_t a1 = __float_as_uint(sk[kr * SB + d0 + 8 + gid]);
        uint32_t a2 = __float_as_uint(sk[(kr + 4) * SB + d0 + gid]);
        uint32_t a3 = __float_as_uint(sk[(kr + 4) * SB + d0 + 8 + gid]);
        #pragma unroll
        for (int nj = 0; nj < 4; nj++) {
            uint32_t b0 = __float_as_uint(sv[kr * SB + oc + nj * 8 + gid]);
            uint32_t b1 = __float_as_uint(sv[(kr + 4) * SB + oc + nj * 8 + gid]);
            mma8(cD[nj], a0, a1, a2, a3, b0, b1);
        }
    }

    float* dst = g_kv + (size_t)b * (DD * MM);
    #pragma unroll
    for (int nj = 0; nj < 4; nj++) {
        int col = oc + nj * 8 + 2 * tg;
        *(float2*)(dst + (d0 + gid) * MM + col)     = make_float2(cD[nj][0], cD[nj][1]);
        *(float2*)(dst + (d0 + 8 + gid) * MM + col) = make_float2(cD[nj][2], cD[nj][3]);
    }

    __syncthreads();
    if (tid < 64)
        g_ks[(size_t)b * DD + tid] = sred[tid] + sred[64 + tid] + sred[128 + tid] + sred[192 + tid];
}

// ---------------------------------------------------------------------------
// k_scan: exclusive prefix over g (elementwise) + ksum prefix. grid (64,4)x256.
// Prefetch double-buffer to break per-g load->use chain.
// ---------------------------------------------------------------------------
__global__ __launch_bounds__(256, 4)
void k_scan() {
    const int nh = blockIdx.x, n = nh >> 4, h = nh & 15;
    const int pos = blockIdx.y * 1024 + threadIdx.x * 4;
    const size_t stride = (size_t)GG * HH * DD * MM;   // unused helper
    (void)stride;
    float4 acc = make_float4(0.f, 0.f, 0.f, 0.f);
    size_t base0 = ((size_t)((n * GG + 0) * HH + h)) * (DD * MM) + pos;
    float4 nxt = *(const float4*)&g_kv[base0];
    for (int g = 0; g < GG; g++) {
        float4 cur = nxt;
        size_t base = ((size_t)((n * GG + g) * HH + h)) * (DD * MM) + pos;
        if (g + 1 < GG) {
            size_t basen = ((size_t)((n * GG + g + 1) * HH + h)) * (DD * MM) + pos;
            nxt = *(const float4*)&g_kv[basen];
        }
        *(float4*)&g_kvp[base] = acc;
        acc.x += cur.x; acc.y += cur.y; acc.z += cur.z; acc.w += cur.w;
    }
    if (blockIdx.y == 0 && threadIdx.x < DD) {
        float a = 0.f;
        for (int g = 0; g < GG; g++) {
            size_t off = (size_t)((n * GG + g) * HH + h) * DD + threadIdx.x;
            g_ksp[off] = a;
            a += g_ks[off];
        }
    }
}

// ---------------------------------------------------------------------------
// k_main: fused per-tile attention. 512 threads, symmetric phases:
//   phase 2: all 16 warps compute S (32x32 tiles), mask, rowsum partials
//   phase 3: all 16 warps O = phi(q)@kvp + S@V (16x32 tiles); warps 0-3 fold z
// ---------------------------------------------------------------------------
#define OFF_SQ   0
#define OFF_SK   (CC*SA)
#define OFF_SV   (OFF_SK + CC*SA)
#define OFF_SS   (OFF_SV + CC*SB)
#define OFF_KVP  (OFF_SS + CC*SSW)
#define OFF_KSP  (OFF_KVP + DD*SB)
#define OFF_ZP   (OFF_KSP + DD)
#define OFF_Z    (OFF_ZP + 4*CC)
#define SM3_FLOATS (OFF_Z + CC)
#define SMEM3  (SM3_FLOATS * 4)

__global__ __launch_bounds__(512, 1)
void k_main(const float* __restrict__ Q, const float* __restrict__ K,
            const float* __restrict__ V, float* __restrict__ O) {
    extern __shared__ float sm[];
    float* sq   = sm + OFF_SQ;
    float* sk   = sm + OFF_SK;
    float* sv   = sm + OFF_SV;
    float* sS   = sm + OFF_SS;
    float* skvp = sm + OFF_KVP;
    float* sksp = sm + OFF_KSP;
    float* szp  = sm + OFF_ZP;    // [4][CC] col-group partial rowsums
    float* sz   = sm + OFF_Z;

    const int tid = threadIdx.x, wid = tid >> 5, lane = tid & 31;
    const int gid = lane >> 2, tg = lane & 3;
    const int b = blockIdx.x, h = b & 15, g = (b >> 4) & 31, n = b >> 9;

    // ---- loads ----
    #pragma unroll
    for (int it = 0; it < 4; it++) {
        int idx = tid + it * 512;
        int r = idx >> 4, c0 = (idx & 15) * 4;
        int gb = ((n * LL + g * CC + r) * HH + h) * DD + c0;
        float4 q4 = *(const float4*)(Q + gb);
        float4 k4 = *(const float4*)(K + gb);
        float4 v4 = *(const float4*)(V + gb);
        sq[r * SA + c0 + 0] = f2tf(phi(q4.x));
        sq[r * SA + c0 + 1] = f2tf(phi(q4.y));
        sq[r * SA + c0 + 2] = f2tf(phi(q4.z));
        sq[r * SA + c0 + 3] = f2tf(phi(q4.w));
        sk[r * SA + c0 + 0] = f2tf(phi(k4.x));
        sk[r * SA + c0 + 1] = f2tf(phi(k4.y));
        sk[r * SA + c0 + 2] = f2tf(phi(k4.z));
        sk[r * SA + c0 + 3] = f2tf(phi(k4.w));
        sv[r * SB + c0 + 0] = f2tf(v4.x);
        sv[r * SB + c0 + 1] = f2tf(v4.y);
        sv[r * SB + c0 + 2] = f2tf(v4.z);
        sv[r * SB + c0 + 3] = f2tf(v4.w);
    }
    {
        const float* src = g_kvp + (size_t)b * (DD * MM);
        #pragma unroll
        for (int it = 0; it < 2; it++) {
            int idx = tid + it * 512;
            int d = idx >> 4, m0 = (idx & 15) * 4;
            float4 s4 = *(const float4*)(src + d * MM + m0);
            skvp[d * SB + m0 + 0] = f2tf(s4.x);
            skvp[d * SB + m0 + 1] = f2tf(s4.y);
            skvp[d * SB + m0 + 2] = f2tf(s4.z);
            skvp[d * SB + m0 + 3] = f2tf(s4.w);
        }
        if (tid < DD) sksp[tid] = g_ksp[(size_t)b * DD + tid];
    }
    __syncthreads();   // (A)

    // ---- phase 2: S tiles 32x32 per warp (4x4 grid of warps) ----
    {
        const int r0 = (wid >> 2) * 32, c0g = (wid & 3) * 32, cg = wid & 3;
        float cS[2][4][4];
        #pragma unroll
        for (int mi = 0; mi < 2; mi++)
            #pragma unroll
            for (int nj = 0; nj < 4; nj++)
                #pragma unroll
                for (int q = 0; q < 4; q++) cS[mi][nj][q] = 0.f;

        #pragma unroll
        for (int kk = 0; kk < 8; kk++) {
            int kc = kk * 8 + tg;
            uint32_t a[2][4];
            #pragma unroll
            for (int mi = 0; mi < 2; mi++) {
                int ar = r0 + mi * 16;
                a[mi][0] = __float_as_uint(sq[(ar + gid) * SA + kc]);
                a[mi][1] = __float_as_uint(sq[(ar + 8 + gid) * SA + kc]);
                a[mi][2] = __float_as_uint(sq[(ar + gid) * SA + kc + 4]);
                a[mi][3] = __float_as_uint(sq[(ar + 8 + gid) * SA + kc + 4]);
            }
            #pragma unroll
            for (int nj = 0; nj < 4; nj++) {
                uint32_t b0 = __float_as_uint(sk[(c0g + nj * 8 + gid) * SA + kc]);
                uint32_t b1 = __float_as_uint(sk[(c0g + nj * 8 + gid) * SA + kc + 4]);
                mma8(cS[0][nj], a[0][0], a[0][1], a[0][2], a[0][3], b0, b1);
                mma8(cS[1][nj], a[1][0], a[1][1], a[1][2], a[1][3], b0, b1);
            }
        }

        // mask, rowsum partials, store masked S
        #pragma unroll
        for (int mi = 0; mi < 2; mi++) {
            int rlo = r0 + mi * 16 + gid, rhi = rlo + 8;
            float zlo = 0.f, zhi = 0.f;
            #pragma unroll
            for (int nj = 0; nj < 4; nj++) {
                int c0 = c0g + nj * 8 + 2 * tg, c1 = c0 + 1;
                float s0 = (c0 <= rlo) ? cS[mi][nj][0] : 0.f;
                float s1 = (c1 <= rlo) ? cS[mi][nj][1] : 0.f;
                float s2 = (c0 <= rhi) ? cS[mi][nj][2] : 0.f;
                float s3 = (c1 <= rhi) ? cS[mi][nj][3] : 0.f;
                zlo += s0 + s1;
                zhi += s2 + s3;
                *(float2*)&sS[rlo * SSW + c0] = make_float2(f2tf(s0), f2tf(s1));
                *(float2*)&sS[rhi * SSW + c0] = make_float2(f2tf(s2), f2tf(s3));
            }
            zlo += __shfl_xor_sync(0xffffffffu, zlo, 1);
            zlo += __shfl_xor_sync(0xffffffffu, zlo, 2);
            zhi += __shfl_xor_sync(0xffffffffu, zhi, 1);
            zhi += __shfl_xor_sync(0xffffffffu, zhi, 2);
            if (tg == 0) {
                szp[cg * CC + rlo] = zlo;
                szp[cg * CC + rhi] = zhi;
            }
        }
    }
    __syncthreads();   // (B)

    // ---- phase 3: O tiles 16x32 per warp (8x2 grid), K = 64(inter) + 128(intra) ----
    const int ro = (wid >> 1) * 16, oc = (wid & 1) * 32;
    float cO[4][4];
    #pragma unroll
    for (int nj = 0; nj < 4; nj++)
        #pragma unroll
        for (int q = 0; q < 4; q++) cO[nj][q] = 0.f;

    // inter: phi(q) @ kvp
    #pragma unroll
    for (int kk = 0; kk < 8; kk++) {
        int kc = kk * 8 + tg;
        uint32_t a0 = __float_as_uint(sq[(ro + gid) * SA + kc]);
        uint32_t a1 = __float_as_uint(sq[(ro + 8 + gid) * SA + kc]);
        uint32_t a2 = __float_as_uint(sq[(ro + gid) * SA + kc + 4]);
        uint32_t a3 = __float_as_uint(sq[(ro + 8 + gid) * SA + kc + 4]);
        #pragma unroll
        for (int nj = 0; nj < 4; nj++) {
            uint32_t b0 = __float_as_uint(skvp[kc * SB + oc + nj * 8 + gid]);
            uint32_t b1 = __float_as_uint(skvp[(kc + 4) * SB + oc + nj * 8 + gid]);
            mma8(cO[nj], a0, a1, a2, a3, b0, b1);
        }
    }

    // z on warps 0-3 (overlapped with other warps' intra GEMM)
    if (tid < CC) {
        float qd = EPS;
        #pragma unroll 8
        for (int d = 0; d < DD; d++) qd += sq[tid * SA + d] * sksp[d];
        sz[tid] = szp[tid] + szp[CC + tid] + szp[2 * CC + tid] + szp[3 * CC + tid] + qd;
    }

    // intra: S_masked @ V
    #pragma unroll
    for (int kk = 0; kk < 16; kk++) {
        int kc = kk * 8 + tg;
        uint32_t a0 = __float_as_uint(sS[(ro + gid) * SSW + kc]);
        uint32_t a1 = __float_as_uint(sS[(ro + 8 + gid) * SSW + kc]);
        uint32_t a2 = __float_as_uint(sS[(ro + gid) * SSW + kc + 4]);
        uint32_t a3 = __float_as_uint(sS[(ro + 8 + gid) * SSW + kc + 4]);
        #pragma unroll
        for (int nj = 0; nj < 4; nj++) {
            uint32_t b0 = __float_as_uint(sv[kc * SB + oc + nj * 8 + gid]);
            uint32_t b1 = __float_as_uint(sv[(kc + 4) * SB + oc + nj * 8 + gid]);
            mma8(cO[nj], a0, a1, a2, a3, b0, b1);
        }
    }
    __syncthreads();   // (C): sz visible

    // ---- epilogue ----
    {
        int rlo = ro + gid, rhi = rlo + 8;
        float izlo = 1.f / sz[rlo];
        float izhi = 1.f / sz[rhi];
        float* oblo = O + ((size_t)((n * LL + g * CC + rlo) * HH + h)) * MM;
        float* obhi = O + ((size_t)((n * LL + g * CC + rhi) * HH + h)) * MM;
        #pragma unroll
        for (int nj = 0; nj < 4; nj++) {
            int c0 = oc + nj * 8 + 2 * tg;
            *(float2*)(oblo + c0) = make_float2(cO[nj][0] * izlo, cO[nj][1] * izlo);
            *(float2*)(obhi + c0) = make_float2(cO[nj][2] * izhi, cO[nj][3] * izhi);
        }
    }
}

// ---------------------------------------------------------------------------
extern "C" void kernel_launch(void* const* d_in, const int* in_sizes, int n_in,
                              void* d_out, int out_size) {
    const float* Q = (const float*)d_in[0];
    const float* K = (const float*)d_in[1];
    const float* V = (const float*)d_in[2];
    float* O = (float*)d_out;

    cudaFuncSetAttribute(k_state, cudaFuncAttributeMaxDynamicSharedMemorySize, SMEM1);
    cudaFuncSetAttribute(k_main,  cudaFuncAttributeMaxDynamicSharedMemorySize, SMEM3);

    k_state<<<NTILE, 256, SMEM1>>>(K, V);
    k_scan<<<dim3(NB * HH, 4), 256>>>();
    k_main<<<NTILE, 512, SMEM3>>>(Q, K, V, O);
}